// round 3
// baseline (speedup 1.0000x reference)
#include <cuda_runtime.h>
#include <math.h>

#define NNODES 100000
#define NEDGES 3200000
#define NFEAT  256
#define NHID   128
#define NCLASS 40

// ---------------- scratch ----------------
__device__ float g_Self[(size_t)NNODES * NHID];
__device__ float g_P[(size_t)NNODES * NHID];
__device__ float g_H[(size_t)NNODES * NHID];
__device__ int   g_deg[NNODES];
__device__ int   g_rowptr[NNODES + 1];
__device__ int   g_cursor[NNODES];
__device__ int   g_colidx[NEDGES];
__device__ float g_invdeg[NNODES];

// ---------------- f32x2 helpers (Blackwell packed FMA) ----------------
__device__ __forceinline__ void ffma2(unsigned long long& d,
                                      unsigned long long a,
                                      unsigned long long b) {
    asm("fma.rn.f32x2 %0, %1, %2, %0;" : "+l"(d) : "l"(a), "l"(b));
}
__device__ __forceinline__ unsigned long long dup2(float x) {
    unsigned long long r;
    asm("mov.b64 %0, {%1, %1};" : "=l"(r) : "f"(x));
    return r;
}
__device__ __forceinline__ void unpack2(unsigned long long d, float& lo, float& hi) {
    asm("mov.b64 {%0, %1}, %2;" : "=f"(lo), "=f"(hi) : "l"(d));
}

// ---------------- CSR build ----------------
__global__ void k_zero_deg() {
    int i = blockIdx.x * blockDim.x + threadIdx.x;
    if (i < NNODES) g_deg[i] = 0;
}

__global__ void k_hist(const int* __restrict__ rows, int E) {
    int e = blockIdx.x * blockDim.x + threadIdx.x;
    if (e < E) atomicAdd(&g_deg[rows[e]], 1);
}

__global__ void k_scan() {
    __shared__ int wsum[32];
    __shared__ int carry_s;
    int tid = threadIdx.x, lane = tid & 31, wid = tid >> 5;
    if (tid == 0) carry_s = 0;
    __syncthreads();
    for (int base = 0; base < NNODES; base += 1024) {
        int i = base + tid;
        int v = (i < NNODES) ? g_deg[i] : 0;
        int x = v;
        #pragma unroll
        for (int o = 1; o < 32; o <<= 1) {
            int t = __shfl_up_sync(0xffffffffu, x, o);
            if (lane >= o) x += t;
        }
        if (lane == 31) wsum[wid] = x;
        __syncthreads();
        if (wid == 0) {
            int y = wsum[lane];
            #pragma unroll
            for (int o = 1; o < 32; o <<= 1) {
                int t = __shfl_up_sync(0xffffffffu, y, o);
                if (lane >= o) y += t;
            }
            wsum[lane] = y;
        }
        __syncthreads();
        int incl = x + (wid > 0 ? wsum[wid - 1] : 0) + carry_s;
        if (i < NNODES) g_rowptr[i] = incl - v;
        __syncthreads();
        if (tid == 1023) carry_s = incl;
        __syncthreads();
    }
    if (threadIdx.x == 0) g_rowptr[NNODES] = carry_s;
}

__global__ void k_aux() {
    int i = blockIdx.x * blockDim.x + threadIdx.x;
    if (i < NNODES) {
        g_cursor[i] = g_rowptr[i];
        g_invdeg[i] = 1.0f / ((float)g_deg[i] + 1.0f);
    }
}

__global__ void k_scatter(const int* __restrict__ rows, const int* __restrict__ cols, int E) {
    int e = blockIdx.x * blockDim.x + threadIdx.x;
    if (e < E) {
        int r = rows[e];
        int p = atomicAdd(&g_cursor[r], 1);
        g_colidx[p] = cols[e];
    }
}

// ---------------- SGEMM (FFMA2): C = A[N x K] * B^T, B from two slabs ------
// A tile staged in SMEM pre-duplicated as f32x2 {a,a} pairs.
__global__ __launch_bounds__(256, 2) void sgemm_kernel(
    const float* __restrict__ A,
    const float* __restrict__ B0, const float* __restrict__ B1,
    int K, int ldb, int Msplit, int M,
    float* __restrict__ C0, float* __restrict__ C1,
    int ldc, int Nrows)
{
    __shared__ unsigned long long As2[8][128];   // 8 KB, duplicated A values
    __shared__ float Bs[8][128];                 // 4 KB

    int tid = threadIdx.x;
    int n0 = blockIdx.x * 128;
    int m0 = blockIdx.y * 128;
    int tx = tid & 15, ty = tid >> 4;

    unsigned long long acc2[8][4];
    #pragma unroll
    for (int i = 0; i < 8; i++)
        #pragma unroll
        for (int j = 0; j < 4; j++) acc2[i][j] = 0ull;

    int aRow = tid >> 1;
    int aCol = (tid & 1) * 4;
    bool aValid = (n0 + aRow) < Nrows;
    const float* Aptr = A + (size_t)(n0 + aRow) * K + aCol;

    int bRow = tid >> 1;
    int bCol = (tid & 1) * 4;
    int m = m0 + bRow;
    const float* Bptr = nullptr;
    if (m < M)
        Bptr = (m < Msplit ? B0 + (size_t)m * ldb
                           : B1 + (size_t)(m - Msplit) * ldb) + bCol;

    for (int k0 = 0; k0 < K; k0 += 8) {
        float4 av = aValid ? *reinterpret_cast<const float4*>(Aptr + k0)
                           : make_float4(0.f, 0.f, 0.f, 0.f);
        float4 bv = Bptr ? *reinterpret_cast<const float4*>(Bptr + k0)
                         : make_float4(0.f, 0.f, 0.f, 0.f);
        As2[aCol + 0][aRow] = dup2(av.x);
        As2[aCol + 1][aRow] = dup2(av.y);
        As2[aCol + 2][aRow] = dup2(av.z);
        As2[aCol + 3][aRow] = dup2(av.w);
        Bs[bCol + 0][bRow] = bv.x; Bs[bCol + 1][bRow] = bv.y;
        Bs[bCol + 2][bRow] = bv.z; Bs[bCol + 3][bRow] = bv.w;
        __syncthreads();

        #pragma unroll
        for (int k = 0; k < 8; k++) {
            unsigned long long a2[8];
            *reinterpret_cast<ulonglong2*>(a2)     = *reinterpret_cast<ulonglong2*>(&As2[k][ty * 8]);
            *reinterpret_cast<ulonglong2*>(a2 + 2) = *reinterpret_cast<ulonglong2*>(&As2[k][ty * 8 + 2]);
            *reinterpret_cast<ulonglong2*>(a2 + 4) = *reinterpret_cast<ulonglong2*>(&As2[k][ty * 8 + 4]);
            *reinterpret_cast<ulonglong2*>(a2 + 6) = *reinterpret_cast<ulonglong2*>(&As2[k][ty * 8 + 6]);
            unsigned long long b2[4];
            *reinterpret_cast<ulonglong2*>(b2)     = *reinterpret_cast<ulonglong2*>(&Bs[k][tx * 8]);
            *reinterpret_cast<ulonglong2*>(b2 + 2) = *reinterpret_cast<ulonglong2*>(&Bs[k][tx * 8 + 4]);
            #pragma unroll
            for (int i = 0; i < 8; i++)
                #pragma unroll
                for (int j = 0; j < 4; j++)
                    ffma2(acc2[i][j], a2[i], b2[j]);
        }
        __syncthreads();
    }

    #pragma unroll
    for (int i = 0; i < 8; i++) {
        int row = n0 + ty * 8 + i;
        if (row >= Nrows) continue;
        #pragma unroll
        for (int j = 0; j < 4; j++) {
            float lo, hi;
            unpack2(acc2[i][j], lo, hi);
            int mm0 = m0 + tx * 8 + 2 * j;
            int mm1 = mm0 + 1;
            if (mm0 < M) {
                if (mm0 < Msplit) C0[(size_t)row * ldc + mm0] = lo;
                else              C1[(size_t)row * ldc + (mm0 - Msplit)] = lo;
            }
            if (mm1 < M) {
                if (mm1 < Msplit) C0[(size_t)row * ldc + mm1] = hi;
                else              C1[(size_t)row * ldc + (mm1 - Msplit)] = hi;
            }
        }
    }
}

// ---------------- Classifier GEMM fused with bias + log_softmax -------------
// out[row, 0:40] = log_softmax(A[row] @ W^T + bias). Tile 128 rows x 64 cols.
__global__ __launch_bounds__(256, 2) void cls_kernel(
    const float* __restrict__ A, const float* __restrict__ W,
    const float* __restrict__ bias, float* __restrict__ out, int Nrows)
{
    __shared__ float As[8][128];
    __shared__ float Bs[8][64];

    int tid = threadIdx.x;
    int n0 = blockIdx.x * 128;
    int tx = tid & 15, ty = tid >> 4;

    float acc[8][4];
    #pragma unroll
    for (int i = 0; i < 8; i++)
        #pragma unroll
        for (int j = 0; j < 4; j++) acc[i][j] = 0.f;

    int aRow = tid >> 1;
    int aCol = (tid & 1) * 4;
    bool aValid = (n0 + aRow) < Nrows;
    const float* Aptr = A + (size_t)(n0 + aRow) * NHID + aCol;

    int bRow = tid >> 1;           // 0..63 for tid<128
    int bCol = (tid & 1) * 4;
    const float* Bptr = (tid < 128 && bRow < NCLASS) ? W + (size_t)bRow * NHID + bCol : nullptr;

    for (int k0 = 0; k0 < NHID; k0 += 8) {
        float4 av = aValid ? *reinterpret_cast<const float4*>(Aptr + k0)
                           : make_float4(0.f, 0.f, 0.f, 0.f);
        As[aCol + 0][aRow] = av.x; As[aCol + 1][aRow] = av.y;
        As[aCol + 2][aRow] = av.z; As[aCol + 3][aRow] = av.w;
        if (tid < 128) {
            float4 bv = Bptr ? *reinterpret_cast<const float4*>(Bptr + k0)
                             : make_float4(0.f, 0.f, 0.f, 0.f);
            Bs[bCol + 0][bRow] = bv.x; Bs[bCol + 1][bRow] = bv.y;
            Bs[bCol + 2][bRow] = bv.z; Bs[bCol + 3][bRow] = bv.w;
        }
        __syncthreads();

        #pragma unroll
        for (int k = 0; k < 8; k++) {
            float a[8], b[4];
            *reinterpret_cast<float4*>(a)     = *reinterpret_cast<float4*>(&As[k][ty * 8]);
            *reinterpret_cast<float4*>(a + 4) = *reinterpret_cast<float4*>(&As[k][ty * 8 + 4]);
            *reinterpret_cast<float4*>(b)     = *reinterpret_cast<float4*>(&Bs[k][tx * 4]);
            #pragma unroll
            for (int i = 0; i < 8; i++)
                #pragma unroll
                for (int j = 0; j < 4; j++)
                    acc[i][j] = fmaf(a[i], b[j], acc[i][j]);
        }
        __syncthreads();
    }

    // bias for this thread's 4 columns
    float bs[4];
    #pragma unroll
    for (int j = 0; j < 4; j++) {
        int c = tx * 4 + j;
        bs[j] = (c < NCLASS) ? bias[c] : 0.f;
    }

    // log_softmax per row: 40 logits live across the 16-lane half-warp (same ty)
    #pragma unroll
    for (int i = 0; i < 8; i++) {
        int row = n0 + ty * 8 + i;
        float l[4];
        #pragma unroll
        for (int j = 0; j < 4; j++) {
            int c = tx * 4 + j;
            l[j] = (c < NCLASS) ? acc[i][j] + bs[j] : -INFINITY;
        }
        float mx = fmaxf(fmaxf(l[0], l[1]), fmaxf(l[2], l[3]));
        #pragma unroll
        for (int o = 8; o > 0; o >>= 1)
            mx = fmaxf(mx, __shfl_xor_sync(0xffffffffu, mx, o));
        float se = 0.f;
        #pragma unroll
        for (int j = 0; j < 4; j++) {
            int c = tx * 4 + j;
            if (c < NCLASS) se += __expf(l[j] - mx);
        }
        #pragma unroll
        for (int o = 8; o > 0; o >>= 1)
            se += __shfl_xor_sync(0xffffffffu, se, o);
        float ls = mx + __logf(se);
        if (row < Nrows) {
            #pragma unroll
            for (int j = 0; j < 4; j++) {
                int c = tx * 4 + j;
                if (c < NCLASS) out[(size_t)row * NCLASS + c] = l[j] - ls;
            }
        }
    }
}

// ---------------- CSR SpMM fused with SAGE epilogue ----------------
__global__ void spmm_relu_kernel(const float* __restrict__ P,
                                 const float* __restrict__ S,
                                 float* __restrict__ H)
{
    int warp = (blockIdx.x * blockDim.x + threadIdx.x) >> 5;
    int lane = threadIdx.x & 31;
    if (warp >= NNODES) return;
    int r = warp;
    int start = g_rowptr[r], end = g_rowptr[r + 1];

    float4 acc = make_float4(0.f, 0.f, 0.f, 0.f);
    for (int base = start; base < end; base += 32) {
        int idx = base + lane;
        int c = (idx < end) ? g_colidx[idx] : 0;
        int cnt = min(32, end - base);
        #pragma unroll 4
        for (int j = 0; j < cnt; j++) {
            int cj = __shfl_sync(0xffffffffu, c, j);
            float4 v = *reinterpret_cast<const float4*>(P + (size_t)cj * 128 + lane * 4);
            acc.x += v.x; acc.y += v.y; acc.z += v.z; acc.w += v.w;
        }
    }
    float inv = g_invdeg[r];
    float4 s = *reinterpret_cast<const float4*>(S + (size_t)r * 128 + lane * 4);
    float4 h;
    h.x = fmaxf(fmaf(acc.x, inv, s.x), 0.f);
    h.y = fmaxf(fmaf(acc.y, inv, s.y), 0.f);
    h.z = fmaxf(fmaf(acc.z, inv, s.z), 0.f);
    h.w = fmaxf(fmaf(acc.w, inv, s.w), 0.f);
    *reinterpret_cast<float4*>(H + (size_t)r * 128 + lane * 4) = h;
}

// ---------------- launch ----------------
extern "C" void kernel_launch(void* const* d_in, const int* in_sizes, int n_in,
                              void* d_out, int out_size) {
    const float* x     = (const float*)d_in[0];
    const float* W1    = (const float*)d_in[1];
    const float* W2    = (const float*)d_in[2];
    const float* mlpW  = (const float*)d_in[3];
    const float* mlpb  = (const float*)d_in[4];
    const int*   erow  = (const int*)d_in[5];
    const int*   ecol  = (const int*)d_in[6];
    int E = in_sizes[5];
    float* out = (float*)d_out;

    float *pSelf, *pP, *pH;
    cudaGetSymbolAddress((void**)&pSelf, g_Self);
    cudaGetSymbolAddress((void**)&pP, g_P);
    cudaGetSymbolAddress((void**)&pH, g_H);

    const int nb_nodes = (NNODES + 255) / 256;
    const int nb_edges = (E + 255) / 256;
    const int nb_warps = (NNODES * 32 + 255) / 256;

    k_zero_deg<<<nb_nodes, 256>>>();
    k_hist<<<nb_edges, 256>>>(erow, E);
    k_scan<<<1, 1024>>>();
    k_aux<<<nb_nodes, 256>>>();
    k_scatter<<<nb_edges, 256>>>(erow, ecol, E);

    dim3 g1((NNODES + 127) / 128, 2);
    sgemm_kernel<<<g1, 256>>>(x, W1, W1 + NFEAT, NFEAT, 2 * NFEAT, NHID, 2 * NHID,
                              pSelf, pP, NHID, NNODES);
    spmm_relu_kernel<<<nb_warps, 256>>>(pP, pSelf, pH);

    sgemm_kernel<<<g1, 256>>>(pH, W2, W2 + NHID, NHID, 2 * NHID, NHID, 2 * NHID,
                              pSelf, pP, NHID, NNODES);
    spmm_relu_kernel<<<nb_warps, 256>>>(pP, pSelf, pH);

    cls_kernel<<<(NNODES + 127) / 128, 256>>>(pH, mlpW, mlpb, out, NNODES);
}

// round 5
// speedup vs baseline: 1.3963x; 1.3963x over previous
#include <cuda_runtime.h>
#include <cstdint>
#include <math.h>

#define NNODES 100000
#define NEDGES 3200000
#define NFEAT  256
#define NHID   128
#define NCLASS 40

// ---------------- scratch ----------------
__device__ float g_Self[(size_t)NNODES * NHID];
__device__ float g_P[(size_t)NNODES * NHID];
__device__ float g_H[(size_t)NNODES * NHID];
__device__ int   g_deg[NNODES];
__device__ int   g_rowptr[NNODES + 1];
__device__ int   g_cursor[NNODES];
__device__ int   g_colidx[NEDGES];
__device__ float g_invdeg[NNODES];

__device__ __forceinline__ uint32_t f2tf(float x) {
    uint32_t r;
    asm("cvt.rna.tf32.f32 %0, %1;" : "=r"(r) : "f"(x));
    return r;
}

// ---------------- CSR build ----------------
__global__ void k_zero_deg() {
    int i = blockIdx.x * blockDim.x + threadIdx.x;
    if (i < NNODES) g_deg[i] = 0;
}
__global__ void k_hist(const int* __restrict__ rows, int E) {
    int e = blockIdx.x * blockDim.x + threadIdx.x;
    if (e < E) atomicAdd(&g_deg[rows[e]], 1);
}
__global__ void k_scan() {
    __shared__ int wsum[32];
    __shared__ int carry_s;
    int tid = threadIdx.x, lane = tid & 31, wid = tid >> 5;
    if (tid == 0) carry_s = 0;
    __syncthreads();
    for (int base = 0; base < NNODES; base += 1024) {
        int i = base + tid;
        int v = (i < NNODES) ? g_deg[i] : 0;
        int x = v;
        #pragma unroll
        for (int o = 1; o < 32; o <<= 1) {
            int t = __shfl_up_sync(0xffffffffu, x, o);
            if (lane >= o) x += t;
        }
        if (lane == 31) wsum[wid] = x;
        __syncthreads();
        if (wid == 0) {
            int y = wsum[lane];
            #pragma unroll
            for (int o = 1; o < 32; o <<= 1) {
                int t = __shfl_up_sync(0xffffffffu, y, o);
                if (lane >= o) y += t;
            }
            wsum[lane] = y;
        }
        __syncthreads();
        int incl = x + (wid > 0 ? wsum[wid - 1] : 0) + carry_s;
        if (i < NNODES) g_rowptr[i] = incl - v;
        __syncthreads();
        if (tid == 1023) carry_s = incl;
        __syncthreads();
    }
    if (threadIdx.x == 0) g_rowptr[NNODES] = carry_s;
}
__global__ void k_aux() {
    int i = blockIdx.x * blockDim.x + threadIdx.x;
    if (i < NNODES) {
        g_cursor[i] = g_rowptr[i];
        g_invdeg[i] = 1.0f / ((float)g_deg[i] + 1.0f);
    }
}
__global__ void k_scatter(const int* __restrict__ rows, const int* __restrict__ cols, int E) {
    int e = blockIdx.x * blockDim.x + threadIdx.x;
    if (e < E) {
        int r = rows[e];
        int p = atomicAdd(&g_cursor[r], 1);
        g_colidx[p] = cols[e];
    }
}

// ================= tf32 mma.sync GEMM =================
// C_y[tile, 0:128] = A[tile, :] @ (W + y*K slab)^T
// y = blockIdx.y: 0 -> C0 (Self slab), 1 -> C1 (neigh slab).
// W row-major [128, ldb], A row-major [Nrows, K], C row-major [Nrows, 128].
// Block: 256 thr / 8 warps; warp tile 32(m) x 64(n); K chunks of 32 in smem.
__global__ __launch_bounds__(256, 2) void mma_gemm_kernel(
    const float* __restrict__ A, const float* __restrict__ W,
    int K, int ldb,
    float* __restrict__ C0, float* __restrict__ C1, int Nrows)
{
    __shared__ float As[128][36];   // +4 pad: frag LDS hits all 32 banks
    __shared__ float Bs[128][36];

    const int tid = threadIdx.x;
    const int lane = tid & 31, wid = tid >> 5;
    const int warp_m = wid & 3;          // 0..3 -> 32-row slice
    const int warp_n = wid >> 2;         // 0..1 -> 64-col slice
    const int gid = lane >> 2, tig = lane & 3;
    const int tile0 = blockIdx.x * 128;
    const float* Bp = W + (size_t)blockIdx.y * K;   // slab
    float* Cp = blockIdx.y ? C1 : C0;

    float acc[2][8][4];
    #pragma unroll
    for (int mi = 0; mi < 2; mi++)
        #pragma unroll
        for (int ni = 0; ni < 8; ni++)
            #pragma unroll
            for (int q = 0; q < 4; q++) acc[mi][ni][q] = 0.f;

    for (int kc = 0; kc < K; kc += 32) {
        // ---- stage A chunk [128 x 32] and B chunk [128 x 32], tf32-rounded ----
        #pragma unroll
        for (int it = 0; it < 4; it++) {
            int idx = tid + (it << 8);           // 0..1023 float4 slots
            int row = idx >> 3, kq = idx & 7;    // kq: float4 within 32 floats
            int gr = tile0 + row;
            if (gr >= Nrows) gr = Nrows - 1;
            float4 av = *reinterpret_cast<const float4*>(A + (size_t)gr * K + kc + (kq << 2));
            uint4 at;
            at.x = f2tf(av.x); at.y = f2tf(av.y); at.z = f2tf(av.z); at.w = f2tf(av.w);
            *reinterpret_cast<uint4*>(&As[row][kq << 2]) = at;
            float4 bv = *reinterpret_cast<const float4*>(Bp + (size_t)row * ldb + kc + (kq << 2));
            uint4 bt;
            bt.x = f2tf(bv.x); bt.y = f2tf(bv.y); bt.z = f2tf(bv.z); bt.w = f2tf(bv.w);
            *reinterpret_cast<uint4*>(&Bs[row][kq << 2]) = bt;
        }
        __syncthreads();

        #pragma unroll
        for (int kb = 0; kb < 32; kb += 8) {
            // A fragments for the two m16 tiles
            uint32_t a[2][4];
            #pragma unroll
            for (int mi = 0; mi < 2; mi++) {
                int R = warp_m * 32 + mi * 16;
                a[mi][0] = __float_as_uint(As[R + gid][kb + tig]);
                a[mi][1] = __float_as_uint(As[R + gid + 8][kb + tig]);
                a[mi][2] = __float_as_uint(As[R + gid][kb + tig + 4]);
                a[mi][3] = __float_as_uint(As[R + gid + 8][kb + tig + 4]);
            }
            #pragma unroll
            for (int ni = 0; ni < 8; ni++) {
                int n0 = warp_n * 64 + ni * 8;
                uint32_t b0 = __float_as_uint(Bs[n0 + gid][kb + tig]);
                uint32_t b1 = __float_as_uint(Bs[n0 + gid][kb + tig + 4]);
                #pragma unroll
                for (int mi = 0; mi < 2; mi++) {
                    asm volatile(
                        "mma.sync.aligned.m16n8k8.row.col.f32.tf32.tf32.f32 "
                        "{%0,%1,%2,%3}, {%4,%5,%6,%7}, {%8,%9}, {%0,%1,%2,%3};"
                        : "+f"(acc[mi][ni][0]), "+f"(acc[mi][ni][1]),
                          "+f"(acc[mi][ni][2]), "+f"(acc[mi][ni][3])
                        : "r"(a[mi][0]), "r"(a[mi][1]), "r"(a[mi][2]), "r"(a[mi][3]),
                          "r"(b0), "r"(b1));
                }
            }
        }
        __syncthreads();
    }

    // ---- epilogue ----
    #pragma unroll
    for (int mi = 0; mi < 2; mi++) {
        int r0 = tile0 + warp_m * 32 + mi * 16 + gid;
        #pragma unroll
        for (int ni = 0; ni < 8; ni++) {
            int c = warp_n * 64 + ni * 8 + tig * 2;
            if (r0 < Nrows)
                *reinterpret_cast<float2*>(Cp + (size_t)r0 * 128 + c) =
                    make_float2(acc[mi][ni][0], acc[mi][ni][1]);
            if (r0 + 8 < Nrows)
                *reinterpret_cast<float2*>(Cp + (size_t)(r0 + 8) * 128 + c) =
                    make_float2(acc[mi][ni][2], acc[mi][ni][3]);
        }
    }
}

// ---------------- Classifier GEMM fused with bias + log_softmax -------------
__global__ __launch_bounds__(256, 2) void cls_kernel(
    const float* __restrict__ A, const float* __restrict__ W,
    const float* __restrict__ bias, float* __restrict__ out, int Nrows)
{
    __shared__ float As[8][128];
    __shared__ float Bs[8][64];

    int tid = threadIdx.x;
    int n0 = blockIdx.x * 128;
    int tx = tid & 15, ty = tid >> 4;

    float acc[8][4];
    #pragma unroll
    for (int i = 0; i < 8; i++)
        #pragma unroll
        for (int j = 0; j < 4; j++) acc[i][j] = 0.f;

    int aRow = tid >> 1;
    int aCol = (tid & 1) * 4;
    bool aValid = (n0 + aRow) < Nrows;
    const float* Aptr = A + (size_t)(n0 + aRow) * NHID + aCol;

    int bRow = tid >> 1;
    int bCol = (tid & 1) * 4;
    const float* Bptr = (tid < 128 && bRow < NCLASS) ? W + (size_t)bRow * NHID + bCol : nullptr;

    for (int k0 = 0; k0 < NHID; k0 += 8) {
        float4 av = aValid ? *reinterpret_cast<const float4*>(Aptr + k0)
                           : make_float4(0.f, 0.f, 0.f, 0.f);
        As[aCol + 0][aRow] = av.x; As[aCol + 1][aRow] = av.y;
        As[aCol + 2][aRow] = av.z; As[aCol + 3][aRow] = av.w;
        if (tid < 128) {
            float4 bv = Bptr ? *reinterpret_cast<const float4*>(Bptr + k0)
                             : make_float4(0.f, 0.f, 0.f, 0.f);
            Bs[bCol + 0][bRow] = bv.x; Bs[bCol + 1][bRow] = bv.y;
            Bs[bCol + 2][bRow] = bv.z; Bs[bCol + 3][bRow] = bv.w;
        }
        __syncthreads();

        #pragma unroll
        for (int k = 0; k < 8; k++) {
            float a[8], b[4];
            *reinterpret_cast<float4*>(a)     = *reinterpret_cast<float4*>(&As[k][ty * 8]);
            *reinterpret_cast<float4*>(a + 4) = *reinterpret_cast<float4*>(&As[k][ty * 8 + 4]);
            *reinterpret_cast<float4*>(b)     = *reinterpret_cast<float4*>(&Bs[k][tx * 4]);
            #pragma unroll
            for (int i = 0; i < 8; i++)
                #pragma unroll
                for (int j = 0; j < 4; j++)
                    acc[i][j] = fmaf(a[i], b[j], acc[i][j]);
        }
        __syncthreads();
    }

    float bs[4];
    #pragma unroll
    for (int j = 0; j < 4; j++) {
        int c = tx * 4 + j;
        bs[j] = (c < NCLASS) ? bias[c] : 0.f;
    }

    #pragma unroll
    for (int i = 0; i < 8; i++) {
        int row = n0 + ty * 8 + i;
        float l[4];
        #pragma unroll
        for (int j = 0; j < 4; j++) {
            int c = tx * 4 + j;
            l[j] = (c < NCLASS) ? acc[i][j] + bs[j] : -INFINITY;
        }
        float mx = fmaxf(fmaxf(l[0], l[1]), fmaxf(l[2], l[3]));
        #pragma unroll
        for (int o = 8; o > 0; o >>= 1)
            mx = fmaxf(mx, __shfl_xor_sync(0xffffffffu, mx, o));
        float se = 0.f;
        #pragma unroll
        for (int j = 0; j < 4; j++) {
            int c = tx * 4 + j;
            if (c < NCLASS) se += __expf(l[j] - mx);
        }
        #pragma unroll
        for (int o = 8; o > 0; o >>= 1)
            se += __shfl_xor_sync(0xffffffffu, se, o);
        float ls = mx + __logf(se);
        if (row < Nrows) {
            #pragma unroll
            for (int j = 0; j < 4; j++) {
                int c = tx * 4 + j;
                if (c < NCLASS) out[(size_t)row * NCLASS + c] = l[j] - ls;
            }
        }
    }
}

// ---------------- CSR SpMM fused with SAGE epilogue ----------------
__global__ void spmm_relu_kernel(const float* __restrict__ P,
                                 const float* __restrict__ S,
                                 float* __restrict__ H)
{
    int warp = (blockIdx.x * blockDim.x + threadIdx.x) >> 5;
    int lane = threadIdx.x & 31;
    if (warp >= NNODES) return;
    int r = warp;
    int start = g_rowptr[r], end = g_rowptr[r + 1];

    float4 acc = make_float4(0.f, 0.f, 0.f, 0.f);
    for (int base = start; base < end; base += 32) {
        int idx = base + lane;
        int c = (idx < end) ? g_colidx[idx] : 0;
        int cnt = min(32, end - base);
        #pragma unroll 4
        for (int j = 0; j < cnt; j++) {
            int cj = __shfl_sync(0xffffffffu, c, j);
            float4 v = *reinterpret_cast<const float4*>(P + (size_t)cj * 128 + lane * 4);
            acc.x += v.x; acc.y += v.y; acc.z += v.z; acc.w += v.w;
        }
    }
    float inv = g_invdeg[r];
    float4 s = *reinterpret_cast<const float4*>(S + (size_t)r * 128 + lane * 4);
    float4 h;
    h.x = fmaxf(fmaf(acc.x, inv, s.x), 0.f);
    h.y = fmaxf(fmaf(acc.y, inv, s.y), 0.f);
    h.z = fmaxf(fmaf(acc.z, inv, s.z), 0.f);
    h.w = fmaxf(fmaf(acc.w, inv, s.w), 0.f);
    *reinterpret_cast<float4*>(H + (size_t)r * 128 + lane * 4) = h;
}

// ---------------- launch ----------------
extern "C" void kernel_launch(void* const* d_in, const int* in_sizes, int n_in,
                              void* d_out, int out_size) {
    const float* x     = (const float*)d_in[0];   // [N,256]
    const float* W1    = (const float*)d_in[1];   // [128,512]
    const float* W2    = (const float*)d_in[2];   // [128,256]
    const float* mlpW  = (const float*)d_in[3];   // [40,128]
    const float* mlpb  = (const float*)d_in[4];   // [40]
    const int*   erow  = (const int*)d_in[5];
    const int*   ecol  = (const int*)d_in[6];
    int E = in_sizes[5];
    float* out = (float*)d_out;

    float *pSelf, *pP, *pH;
    cudaGetSymbolAddress((void**)&pSelf, g_Self);
    cudaGetSymbolAddress((void**)&pP, g_P);
    cudaGetSymbolAddress((void**)&pH, g_H);

    const int nb_nodes = (NNODES + 255) / 256;
    const int nb_edges = (E + 255) / 256;
    const int nb_warps = (NNODES * 32 + 255) / 256;
    const int nb_tiles = (NNODES + 127) / 128;

    k_zero_deg<<<nb_nodes, 256>>>();
    k_hist<<<nb_edges, 256>>>(erow, E);
    k_scan<<<1, 1024>>>();
    k_aux<<<nb_nodes, 256>>>();
    k_scatter<<<nb_edges, 256>>>(erow, ecol, E);

    dim3 g1(nb_tiles, 2);
    // Layer 1: slab0 = W1[:,0:256] (self) -> Self ; slab1 = W1[:,256:512] -> P
    mma_gemm_kernel<<<g1, 256>>>(x, W1, NFEAT, 2 * NFEAT, pSelf, pP, NNODES);
    spmm_relu_kernel<<<nb_warps, 256>>>(pP, pSelf, pH);

    // Layer 2
    mma_gemm_kernel<<<g1, 256>>>(pH, W2, NHID, 2 * NHID, pSelf, pP, NNODES);
    spmm_relu_kernel<<<nb_warps, 256>>>(pP, pSelf, pH);

    cls_kernel<<<(NNODES + 127) / 128, 256>>>(pH, mlpW, mlpb, out, NNODES);
}

// round 7
// speedup vs baseline: 2.1473x; 1.5378x over previous
#include <cuda_runtime.h>
#include <cuda_fp16.h>
#include <cstdint>
#include <math.h>

#define NNODES 100000
#define NEDGES 3200000
#define NFEAT  256
#define NHID   128
#define NCLASS 40

// ---------------- scratch ----------------
__device__ float  g_Self[(size_t)NNODES * NHID];
__device__ __half g_Ph[(size_t)NNODES * NHID];     // neighbor projection, fp16
__device__ float  g_H[(size_t)NNODES * NHID];
__device__ int    g_deg[NNODES];
__device__ int    g_rowptr[NNODES + 1];
__device__ int    g_cursor[NNODES];
__device__ int    g_colidx[NEDGES];
__device__ float  g_invdeg[NNODES];

// ---------------- CSR build ----------------
__global__ void k_zero_deg() {
    int i = blockIdx.x * blockDim.x + threadIdx.x;
    if (i < NNODES) g_deg[i] = 0;
}
__global__ void k_hist(const int* __restrict__ rows, int E) {
    int e = blockIdx.x * blockDim.x + threadIdx.x;
    if (e < E) atomicAdd(&g_deg[rows[e]], 1);
}
__global__ void k_scan() {
    __shared__ int wsum[32];
    __shared__ int carry_s;
    int tid = threadIdx.x, lane = tid & 31, wid = tid >> 5;
    if (tid == 0) carry_s = 0;
    __syncthreads();
    for (int base = 0; base < NNODES; base += 1024) {
        int i = base + tid;
        int v = (i < NNODES) ? g_deg[i] : 0;
        int x = v;
        #pragma unroll
        for (int o = 1; o < 32; o <<= 1) {
            int t = __shfl_up_sync(0xffffffffu, x, o);
            if (lane >= o) x += t;
        }
        if (lane == 31) wsum[wid] = x;
        __syncthreads();
        if (wid == 0) {
            int y = wsum[lane];
            #pragma unroll
            for (int o = 1; o < 32; o <<= 1) {
                int t = __shfl_up_sync(0xffffffffu, y, o);
                if (lane >= o) y += t;
            }
            wsum[lane] = y;
        }
        __syncthreads();
        int incl = x + (wid > 0 ? wsum[wid - 1] : 0) + carry_s;
        if (i < NNODES) g_rowptr[i] = incl - v;
        __syncthreads();
        if (tid == 1023) carry_s = incl;
        __syncthreads();
    }
    if (threadIdx.x == 0) g_rowptr[NNODES] = carry_s;
}
__global__ void k_aux() {
    int i = blockIdx.x * blockDim.x + threadIdx.x;
    if (i < NNODES) {
        g_cursor[i] = g_rowptr[i];
        g_invdeg[i] = 1.0f / ((float)g_deg[i] + 1.0f);
    }
}
__global__ void k_scatter(const int* __restrict__ rows, const int* __restrict__ cols, int E) {
    int e = blockIdx.x * blockDim.x + threadIdx.x;
    if (e < E) {
        int r = rows[e];
        int p = atomicAdd(&g_cursor[r], 1);
        g_colidx[p] = cols[e];
    }
}

// ================= tf32 mma.sync GEMM, cp.async double-buffered =============
// y = blockIdx.y: 0 -> C0 fp32 (self slab of W), 1 -> C1h fp16 (neigh slab).
// W row-major [128, ldb]; A row-major [Nrows, K]; outputs [Nrows, 128].
// Block: 256 thr / 8 warps; warp tile 32(m) x 64(n); K chunks of 32, 2 stages.
// tf32 operands are raw fp32 bits (HW truncates low mantissa bits).
#define ABUF_F 4608            // 128*36 floats per stage
#define SMEM_FLOATS (4 * ABUF_F)
#define GEMM_SMEM_BYTES (SMEM_FLOATS * 4)

__global__ __launch_bounds__(256, 1) void mma_gemm_kernel(
    const float* __restrict__ A, const float* __restrict__ W,
    int K, int ldb,
    float* __restrict__ C0, __half* __restrict__ C1h, int Nrows)
{
    extern __shared__ float smemf[];   // [2][128][36] A, then [2][128][36] B
    const int tid = threadIdx.x;
    const int lane = tid & 31, wid = tid >> 5;
    const int warp_m = wid & 3;
    const int warp_n = wid >> 2;
    const int gid = lane >> 2, tig = lane & 3;
    const int tile0 = blockIdx.x * 128;
    const float* Bp = W + (size_t)blockIdx.y * K;
    const uint32_t smem_u32 = (uint32_t)__cvta_generic_to_shared(smemf);

    float acc[2][8][4];
    #pragma unroll
    for (int mi = 0; mi < 2; mi++)
        #pragma unroll
        for (int ni = 0; ni < 8; ni++)
            #pragma unroll
            for (int q = 0; q < 4; q++) acc[mi][ni][q] = 0.f;

    // staging indices (fixed per thread)
    const int srow = tid >> 3;            // +32 per it
    const int skq  = (tid & 7) << 2;
    int gr0 = tile0 + srow;

    auto stage = [&](int s, int kc) {
        #pragma unroll
        for (int it = 0; it < 4; it++) {
            int row = srow + (it << 5);
            int gr = gr0 + (it << 5);
            if (gr >= Nrows) gr = Nrows - 1;
            const float* ga = A + (size_t)gr * K + kc + skq;
            uint32_t da = smem_u32 + (uint32_t)((s * ABUF_F + row * 36 + skq) << 2);
            asm volatile("cp.async.ca.shared.global [%0], [%1], 16;" :: "r"(da), "l"(ga));
            const float* gb = Bp + (size_t)row * ldb + kc + skq;
            uint32_t db = smem_u32 + (uint32_t)(((2 * ABUF_F) + s * ABUF_F + row * 36 + skq) << 2);
            asm volatile("cp.async.ca.shared.global [%0], [%1], 16;" :: "r"(db), "l"(gb));
        }
        asm volatile("cp.async.commit_group;");
    };

    const int nch = K >> 5;
    stage(0, 0);

    for (int ch = 0; ch < nch; ch++) {
        const int s = ch & 1;
        if (ch + 1 < nch) {
            stage(s ^ 1, (ch + 1) << 5);
            asm volatile("cp.async.wait_group 1;");
        } else {
            asm volatile("cp.async.wait_group 0;");
        }
        __syncthreads();

        const float* Abuf = smemf + s * ABUF_F;
        const float* Bbuf = smemf + 2 * ABUF_F + s * ABUF_F;

        #pragma unroll
        for (int kb = 0; kb < 32; kb += 8) {
            uint32_t a[2][4];
            #pragma unroll
            for (int mi = 0; mi < 2; mi++) {
                int R = warp_m * 32 + mi * 16;
                a[mi][0] = __float_as_uint(Abuf[(R + gid) * 36 + kb + tig]);
                a[mi][1] = __float_as_uint(Abuf[(R + gid + 8) * 36 + kb + tig]);
                a[mi][2] = __float_as_uint(Abuf[(R + gid) * 36 + kb + tig + 4]);
                a[mi][3] = __float_as_uint(Abuf[(R + gid + 8) * 36 + kb + tig + 4]);
            }
            #pragma unroll
            for (int ni = 0; ni < 8; ni++) {
                int n0 = warp_n * 64 + ni * 8;
                uint32_t b0 = __float_as_uint(Bbuf[(n0 + gid) * 36 + kb + tig]);
                uint32_t b1 = __float_as_uint(Bbuf[(n0 + gid) * 36 + kb + tig + 4]);
                #pragma unroll
                for (int mi = 0; mi < 2; mi++) {
                    asm volatile(
                        "mma.sync.aligned.m16n8k8.row.col.f32.tf32.tf32.f32 "
                        "{%0,%1,%2,%3}, {%4,%5,%6,%7}, {%8,%9}, {%0,%1,%2,%3};"
                        : "+f"(acc[mi][ni][0]), "+f"(acc[mi][ni][1]),
                          "+f"(acc[mi][ni][2]), "+f"(acc[mi][ni][3])
                        : "r"(a[mi][0]), "r"(a[mi][1]), "r"(a[mi][2]), "r"(a[mi][3]),
                          "r"(b0), "r"(b1));
                }
            }
        }
        __syncthreads();
    }

    // ---- epilogue: y==0 -> fp32 C0, y==1 -> fp16 C1h ----
    const bool half_out = (blockIdx.y != 0);
    #pragma unroll
    for (int mi = 0; mi < 2; mi++) {
        int r0 = tile0 + warp_m * 32 + mi * 16 + gid;
        #pragma unroll
        for (int ni = 0; ni < 8; ni++) {
            int c = warp_n * 64 + ni * 8 + tig * 2;
            if (half_out) {
                if (r0 < Nrows)
                    *reinterpret_cast<__half2*>(C1h + (size_t)r0 * 128 + c) =
                        __floats2half2_rn(acc[mi][ni][0], acc[mi][ni][1]);
                if (r0 + 8 < Nrows)
                    *reinterpret_cast<__half2*>(C1h + (size_t)(r0 + 8) * 128 + c) =
                        __floats2half2_rn(acc[mi][ni][2], acc[mi][ni][3]);
            } else {
                if (r0 < Nrows)
                    *reinterpret_cast<float2*>(C0 + (size_t)r0 * 128 + c) =
                        make_float2(acc[mi][ni][0], acc[mi][ni][1]);
                if (r0 + 8 < Nrows)
                    *reinterpret_cast<float2*>(C0 + (size_t)(r0 + 8) * 128 + c) =
                        make_float2(acc[mi][ni][2], acc[mi][ni][3]);
            }
        }
    }
}

// ---------------- Classifier GEMM fused with bias + log_softmax -------------
__global__ __launch_bounds__(256, 2) void cls_kernel(
    const float* __restrict__ A, const float* __restrict__ W,
    const float* __restrict__ bias, float* __restrict__ out, int Nrows)
{
    __shared__ float As[8][128];
    __shared__ float Bs[8][64];

    int tid = threadIdx.x;
    int n0 = blockIdx.x * 128;
    int tx = tid & 15, ty = tid >> 4;

    float acc[8][4];
    #pragma unroll
    for (int i = 0; i < 8; i++)
        #pragma unroll
        for (int j = 0; j < 4; j++) acc[i][j] = 0.f;

    int aRow = tid >> 1;
    int aCol = (tid & 1) * 4;
    bool aValid = (n0 + aRow) < Nrows;
    const float* Aptr = A + (size_t)(n0 + aRow) * NHID + aCol;

    int bRow = tid >> 1;
    int bCol = (tid & 1) * 4;
    const float* Bptr = (tid < 128 && bRow < NCLASS) ? W + (size_t)bRow * NHID + bCol : nullptr;

    for (int k0 = 0; k0 < NHID; k0 += 8) {
        float4 av = aValid ? *reinterpret_cast<const float4*>(Aptr + k0)
                           : make_float4(0.f, 0.f, 0.f, 0.f);
        As[aCol + 0][aRow] = av.x; As[aCol + 1][aRow] = av.y;
        As[aCol + 2][aRow] = av.z; As[aCol + 3][aRow] = av.w;
        if (tid < 128) {
            float4 bv = Bptr ? *reinterpret_cast<const float4*>(Bptr + k0)
                             : make_float4(0.f, 0.f, 0.f, 0.f);
            Bs[bCol + 0][bRow] = bv.x; Bs[bCol + 1][bRow] = bv.y;
            Bs[bCol + 2][bRow] = bv.z; Bs[bCol + 3][bRow] = bv.w;
        }
        __syncthreads();

        #pragma unroll
        for (int k = 0; k < 8; k++) {
            float a[8], b[4];
            *reinterpret_cast<float4*>(a)     = *reinterpret_cast<float4*>(&As[k][ty * 8]);
            *reinterpret_cast<float4*>(a + 4) = *reinterpret_cast<float4*>(&As[k][ty * 8 + 4]);
            *reinterpret_cast<float4*>(b)     = *reinterpret_cast<float4*>(&Bs[k][tx * 4]);
            #pragma unroll
            for (int i = 0; i < 8; i++)
                #pragma unroll
                for (int j = 0; j < 4; j++)
                    acc[i][j] = fmaf(a[i], b[j], acc[i][j]);
        }
        __syncthreads();
    }

    float bs[4];
    #pragma unroll
    for (int j = 0; j < 4; j++) {
        int c = tx * 4 + j;
        bs[j] = (c < NCLASS) ? bias[c] : 0.f;
    }

    #pragma unroll
    for (int i = 0; i < 8; i++) {
        int row = n0 + ty * 8 + i;
        float l[4];
        #pragma unroll
        for (int j = 0; j < 4; j++) {
            int c = tx * 4 + j;
            l[j] = (c < NCLASS) ? acc[i][j] + bs[j] : -INFINITY;
        }
        float mx = fmaxf(fmaxf(l[0], l[1]), fmaxf(l[2], l[3]));
        #pragma unroll
        for (int o = 8; o > 0; o >>= 1)
            mx = fmaxf(mx, __shfl_xor_sync(0xffffffffu, mx, o));
        float se = 0.f;
        #pragma unroll
        for (int j = 0; j < 4; j++) {
            int c = tx * 4 + j;
            if (c < NCLASS) se += __expf(l[j] - mx);
        }
        #pragma unroll
        for (int o = 8; o > 0; o >>= 1)
            se += __shfl_xor_sync(0xffffffffu, se, o);
        float ls = mx + __logf(se);
        if (row < Nrows) {
            #pragma unroll
            for (int j = 0; j < 4; j++) {
                int c = tx * 4 + j;
                if (c < NCLASS) out[(size_t)row * NCLASS + c] = l[j] - ls;
            }
        }
    }
}

// ---------------- CSR SpMM (fp16 gather) fused with SAGE epilogue -----------
// H[r] = relu(Self[r] + (sum_{c in N(r)} Ph[c]) * invdeg[r]) ; fp32 accumulate.
__global__ void spmm_relu_kernel(const __half* __restrict__ P,
                                 const float* __restrict__ S,
                                 float* __restrict__ H)
{
    int warp = (blockIdx.x * blockDim.x + threadIdx.x) >> 5;
    int lane = threadIdx.x & 31;
    if (warp >= NNODES) return;
    int r = warp;
    int start = g_rowptr[r], end = g_rowptr[r + 1];

    float4 acc = make_float4(0.f, 0.f, 0.f, 0.f);
    for (int base = start; base < end; base += 32) {
        int idx = base + lane;
        int c = (idx < end) ? g_colidx[idx] : 0;
        int cnt = min(32, end - base);
        #pragma unroll 4
        for (int j = 0; j < cnt; j++) {
            int cj = __shfl_sync(0xffffffffu, c, j);
            uint2 raw = *reinterpret_cast<const uint2*>(P + (size_t)cj * 128 + lane * 4);
            float2 f0 = __half22float2(*reinterpret_cast<__half2*>(&raw.x));
            float2 f1 = __half22float2(*reinterpret_cast<__half2*>(&raw.y));
            acc.x += f0.x; acc.y += f0.y; acc.z += f1.x; acc.w += f1.y;
        }
    }
    float inv = g_invdeg[r];
    float4 s = *reinterpret_cast<const float4*>(S + (size_t)r * 128 + lane * 4);
    float4 h;
    h.x = fmaxf(fmaf(acc.x, inv, s.x), 0.f);
    h.y = fmaxf(fmaf(acc.y, inv, s.y), 0.f);
    h.z = fmaxf(fmaf(acc.z, inv, s.z), 0.f);
    h.w = fmaxf(fmaf(acc.w, inv, s.w), 0.f);
    *reinterpret_cast<float4*>(H + (size_t)r * 128 + lane * 4) = h;
}

// ---------------- launch ----------------
extern "C" void kernel_launch(void* const* d_in, const int* in_sizes, int n_in,
                              void* d_out, int out_size) {
    const float* x     = (const float*)d_in[0];   // [N,256]
    const float* W1    = (const float*)d_in[1];   // [128,512]
    const float* W2    = (const float*)d_in[2];   // [128,256]
    const float* mlpW  = (const float*)d_in[3];   // [40,128]
    const float* mlpb  = (const float*)d_in[4];   // [40]
    const int*   erow  = (const int*)d_in[5];
    const int*   ecol  = (const int*)d_in[6];
    int E = in_sizes[5];
    float* out = (float*)d_out;

    float *pSelf, *pH;
    __half* pPh;
    cudaGetSymbolAddress((void**)&pSelf, g_Self);
    cudaGetSymbolAddress((void**)&pPh, g_Ph);
    cudaGetSymbolAddress((void**)&pH, g_H);

    cudaFuncSetAttribute(mma_gemm_kernel,
                         cudaFuncAttributeMaxDynamicSharedMemorySize, GEMM_SMEM_BYTES);

    const int nb_nodes = (NNODES + 255) / 256;
    const int nb_edges = (E + 255) / 256;
    const int nb_warps = (NNODES * 32 + 255) / 256;
    const int nb_tiles = (NNODES + 127) / 128;

    k_zero_deg<<<nb_nodes, 256>>>();
    k_hist<<<nb_edges, 256>>>(erow, E);
    k_scan<<<1, 1024>>>();
    k_aux<<<nb_nodes, 256>>>();
    k_scatter<<<nb_edges, 256>>>(erow, ecol, E);

    dim3 g1(nb_tiles, 2);
    // Layer 1: y=0 self slab -> Self fp32 ; y=1 neigh slab -> Ph fp16
    mma_gemm_kernel<<<g1, 256, GEMM_SMEM_BYTES>>>(x, W1, NFEAT, 2 * NFEAT,
                                                  pSelf, pPh, NNODES);
    spmm_relu_kernel<<<nb_warps, 256>>>(pPh, pSelf, pH);

    // Layer 2
    mma_gemm_kernel<<<g1, 256, GEMM_SMEM_BYTES>>>(pH, W2, NHID, 2 * NHID,
                                                  pSelf, pPh, NNODES);
    spmm_relu_kernel<<<nb_warps, 256>>>(pPh, pSelf, pH);

    cls_kernel<<<(NNODES + 127) / 128, 256>>>(pH, mlpW, mlpb, out, NNODES);
}

// round 8
// speedup vs baseline: 2.3470x; 1.0930x over previous
#include <cuda_runtime.h>
#include <cuda_fp16.h>
#include <cstdint>
#include <math.h>

#define NNODES 100000
#define NEDGES 3200000
#define NFEAT  256
#define NHID   128
#define NCLASS 40

// ---------------- scratch ----------------
__device__ float  g_Self[(size_t)NNODES * NHID];
__device__ __half g_Ph[(size_t)NNODES * NHID];     // neighbor projection, fp16
__device__ float  g_H[(size_t)NNODES * NHID];
__device__ int    g_deg[NNODES];
__device__ int    g_rowptr[NNODES + 1];
__device__ int    g_cursor[NNODES];
__device__ int    g_colidx[NEDGES];
__device__ float  g_invdeg[NNODES];

// ---------------- CSR build ----------------
__global__ void k_zero_deg() {
    int i = blockIdx.x * blockDim.x + threadIdx.x;
    if (i < NNODES) g_deg[i] = 0;
}
__global__ void k_hist(const int* __restrict__ rows, int E) {
    int e = blockIdx.x * blockDim.x + threadIdx.x;
    if (e < E) atomicAdd(&g_deg[rows[e]], 1);
}
__global__ void k_scan() {
    __shared__ int wsum[32];
    __shared__ int carry_s;
    int tid = threadIdx.x, lane = tid & 31, wid = tid >> 5;
    if (tid == 0) carry_s = 0;
    __syncthreads();
    for (int base = 0; base < NNODES; base += 1024) {
        int i = base + tid;
        int v = (i < NNODES) ? g_deg[i] : 0;
        int x = v;
        #pragma unroll
        for (int o = 1; o < 32; o <<= 1) {
            int t = __shfl_up_sync(0xffffffffu, x, o);
            if (lane >= o) x += t;
        }
        if (lane == 31) wsum[wid] = x;
        __syncthreads();
        if (wid == 0) {
            int y = wsum[lane];
            #pragma unroll
            for (int o = 1; o < 32; o <<= 1) {
                int t = __shfl_up_sync(0xffffffffu, y, o);
                if (lane >= o) y += t;
            }
            wsum[lane] = y;
        }
        __syncthreads();
        int incl = x + (wid > 0 ? wsum[wid - 1] : 0) + carry_s;
        if (i < NNODES) g_rowptr[i] = incl - v;
        __syncthreads();
        if (tid == 1023) carry_s = incl;
        __syncthreads();
    }
    if (threadIdx.x == 0) g_rowptr[NNODES] = carry_s;
}
__global__ void k_aux() {
    int i = blockIdx.x * blockDim.x + threadIdx.x;
    if (i < NNODES) {
        g_cursor[i] = g_rowptr[i];
        g_invdeg[i] = 1.0f / ((float)g_deg[i] + 1.0f);
    }
}
__global__ void k_scatter(const int* __restrict__ rows, const int* __restrict__ cols, int E) {
    int e = blockIdx.x * blockDim.x + threadIdx.x;
    if (e < E) {
        int r = rows[e];
        int p = atomicAdd(&g_cursor[r], 1);
        g_colidx[p] = cols[e];
    }
}

// ================= tf32 mma.sync GEMM, cp.async double-buffered =============
// y = blockIdx.y: 0 -> C0 fp32 (self slab of W), 1 -> C1h fp16 (neigh slab).
// Block: 256 thr / 8 warps; warp tile 32(m) x 64(n); K chunks of 32, 2 stages.
// tf32 operands are raw fp32 bits (HW truncates low mantissa bits).
#define ABUF_F 4608            // 128*36 floats per stage
#define SMEM_FLOATS (4 * ABUF_F)
#define GEMM_SMEM_BYTES (SMEM_FLOATS * 4)

__global__ __launch_bounds__(256, 2) void mma_gemm_kernel(
    const float* __restrict__ A, const float* __restrict__ W,
    int K, int ldb,
    float* __restrict__ C0, __half* __restrict__ C1h, int Nrows)
{
    extern __shared__ float smemf[];   // [2][128][36] A, then [2][128][36] B
    const int tid = threadIdx.x;
    const int lane = tid & 31, wid = tid >> 5;
    const int warp_m = wid & 3;
    const int warp_n = wid >> 2;
    const int gid = lane >> 2, tig = lane & 3;
    const int tile0 = blockIdx.x * 128;
    const float* Bp = W + (size_t)blockIdx.y * K;
    const uint32_t smem_u32 = (uint32_t)__cvta_generic_to_shared(smemf);

    float acc[2][8][4];
    #pragma unroll
    for (int mi = 0; mi < 2; mi++)
        #pragma unroll
        for (int ni = 0; ni < 8; ni++)
            #pragma unroll
            for (int q = 0; q < 4; q++) acc[mi][ni][q] = 0.f;

    const int srow = tid >> 3;
    const int skq  = (tid & 7) << 2;
    int gr0 = tile0 + srow;

    auto stage = [&](int s, int kc) {
        #pragma unroll
        for (int it = 0; it < 4; it++) {
            int row = srow + (it << 5);
            int gr = gr0 + (it << 5);
            if (gr >= Nrows) gr = Nrows - 1;
            const float* ga = A + (size_t)gr * K + kc + skq;
            uint32_t da = smem_u32 + (uint32_t)((s * ABUF_F + row * 36 + skq) << 2);
            asm volatile("cp.async.ca.shared.global [%0], [%1], 16;" :: "r"(da), "l"(ga));
            const float* gb = Bp + (size_t)row * ldb + kc + skq;
            uint32_t db = smem_u32 + (uint32_t)(((2 * ABUF_F) + s * ABUF_F + row * 36 + skq) << 2);
            asm volatile("cp.async.ca.shared.global [%0], [%1], 16;" :: "r"(db), "l"(gb));
        }
        asm volatile("cp.async.commit_group;");
    };

    const int nch = K >> 5;
    stage(0, 0);

    for (int ch = 0; ch < nch; ch++) {
        const int s = ch & 1;
        if (ch + 1 < nch) {
            stage(s ^ 1, (ch + 1) << 5);
            asm volatile("cp.async.wait_group 1;");
        } else {
            asm volatile("cp.async.wait_group 0;");
        }
        __syncthreads();

        const float* Abuf = smemf + s * ABUF_F;
        const float* Bbuf = smemf + 2 * ABUF_F + s * ABUF_F;

        #pragma unroll
        for (int kb = 0; kb < 32; kb += 8) {
            uint32_t a[2][4];
            #pragma unroll
            for (int mi = 0; mi < 2; mi++) {
                int R = warp_m * 32 + mi * 16;
                a[mi][0] = __float_as_uint(Abuf[(R + gid) * 36 + kb + tig]);
                a[mi][1] = __float_as_uint(Abuf[(R + gid + 8) * 36 + kb + tig]);
                a[mi][2] = __float_as_uint(Abuf[(R + gid) * 36 + kb + tig + 4]);
                a[mi][3] = __float_as_uint(Abuf[(R + gid + 8) * 36 + kb + tig + 4]);
            }
            #pragma unroll
            for (int ni = 0; ni < 8; ni++) {
                int n0 = warp_n * 64 + ni * 8;
                uint32_t b0 = __float_as_uint(Bbuf[(n0 + gid) * 36 + kb + tig]);
                uint32_t b1 = __float_as_uint(Bbuf[(n0 + gid) * 36 + kb + tig + 4]);
                #pragma unroll
                for (int mi = 0; mi < 2; mi++) {
                    asm volatile(
                        "mma.sync.aligned.m16n8k8.row.col.f32.tf32.tf32.f32 "
                        "{%0,%1,%2,%3}, {%4,%5,%6,%7}, {%8,%9}, {%0,%1,%2,%3};"
                        : "+f"(acc[mi][ni][0]), "+f"(acc[mi][ni][1]),
                          "+f"(acc[mi][ni][2]), "+f"(acc[mi][ni][3])
                        : "r"(a[mi][0]), "r"(a[mi][1]), "r"(a[mi][2]), "r"(a[mi][3]),
                          "r"(b0), "r"(b1));
                }
            }
        }
        __syncthreads();
    }

    const bool half_out = (blockIdx.y != 0);
    #pragma unroll
    for (int mi = 0; mi < 2; mi++) {
        int r0 = tile0 + warp_m * 32 + mi * 16 + gid;
        #pragma unroll
        for (int ni = 0; ni < 8; ni++) {
            int c = warp_n * 64 + ni * 8 + tig * 2;
            if (half_out) {
                if (r0 < Nrows)
                    *reinterpret_cast<__half2*>(C1h + (size_t)r0 * 128 + c) =
                        __floats2half2_rn(acc[mi][ni][0], acc[mi][ni][1]);
                if (r0 + 8 < Nrows)
                    *reinterpret_cast<__half2*>(C1h + (size_t)(r0 + 8) * 128 + c) =
                        __floats2half2_rn(acc[mi][ni][2], acc[mi][ni][3]);
            } else {
                if (r0 < Nrows)
                    *reinterpret_cast<float2*>(C0 + (size_t)r0 * 128 + c) =
                        make_float2(acc[mi][ni][0], acc[mi][ni][1]);
                if (r0 + 8 < Nrows)
                    *reinterpret_cast<float2*>(C0 + (size_t)(r0 + 8) * 128 + c) =
                        make_float2(acc[mi][ni][2], acc[mi][ni][3]);
            }
        }
    }
}

// ---------------- Classifier GEMM fused with bias + log_softmax -------------
__global__ __launch_bounds__(256, 2) void cls_kernel(
    const float* __restrict__ A, const float* __restrict__ W,
    const float* __restrict__ bias, float* __restrict__ out, int Nrows)
{
    __shared__ float As[8][128];
    __shared__ float Bs[8][64];

    int tid = threadIdx.x;
    int n0 = blockIdx.x * 128;
    int tx = tid & 15, ty = tid >> 4;

    float acc[8][4];
    #pragma unroll
    for (int i = 0; i < 8; i++)
        #pragma unroll
        for (int j = 0; j < 4; j++) acc[i][j] = 0.f;

    int aRow = tid >> 1;
    int aCol = (tid & 1) * 4;
    bool aValid = (n0 + aRow) < Nrows;
    const float* Aptr = A + (size_t)(n0 + aRow) * NHID + aCol;

    int bRow = tid >> 1;
    int bCol = (tid & 1) * 4;
    const float* Bptr = (tid < 128 && bRow < NCLASS) ? W + (size_t)bRow * NHID + bCol : nullptr;

    for (int k0 = 0; k0 < NHID; k0 += 8) {
        float4 av = aValid ? *reinterpret_cast<const float4*>(Aptr + k0)
                           : make_float4(0.f, 0.f, 0.f, 0.f);
        As[aCol + 0][aRow] = av.x; As[aCol + 1][aRow] = av.y;
        As[aCol + 2][aRow] = av.z; As[aCol + 3][aRow] = av.w;
        if (tid < 128) {
            float4 bv = Bptr ? *reinterpret_cast<const float4*>(Bptr + k0)
                             : make_float4(0.f, 0.f, 0.f, 0.f);
            Bs[bCol + 0][bRow] = bv.x; Bs[bCol + 1][bRow] = bv.y;
            Bs[bCol + 2][bRow] = bv.z; Bs[bCol + 3][bRow] = bv.w;
        }
        __syncthreads();

        #pragma unroll
        for (int k = 0; k < 8; k++) {
            float a[8], b[4];
            *reinterpret_cast<float4*>(a)     = *reinterpret_cast<float4*>(&As[k][ty * 8]);
            *reinterpret_cast<float4*>(a + 4) = *reinterpret_cast<float4*>(&As[k][ty * 8 + 4]);
            *reinterpret_cast<float4*>(b)     = *reinterpret_cast<float4*>(&Bs[k][tx * 4]);
            #pragma unroll
            for (int i = 0; i < 8; i++)
                #pragma unroll
                for (int j = 0; j < 4; j++)
                    acc[i][j] = fmaf(a[i], b[j], acc[i][j]);
        }
        __syncthreads();
    }

    float bs[4];
    #pragma unroll
    for (int j = 0; j < 4; j++) {
        int c = tx * 4 + j;
        bs[j] = (c < NCLASS) ? bias[c] : 0.f;
    }

    #pragma unroll
    for (int i = 0; i < 8; i++) {
        int row = n0 + ty * 8 + i;
        float l[4];
        #pragma unroll
        for (int j = 0; j < 4; j++) {
            int c = tx * 4 + j;
            l[j] = (c < NCLASS) ? acc[i][j] + bs[j] : -INFINITY;
        }
        float mx = fmaxf(fmaxf(l[0], l[1]), fmaxf(l[2], l[3]));
        #pragma unroll
        for (int o = 8; o > 0; o >>= 1)
            mx = fmaxf(mx, __shfl_xor_sync(0xffffffffu, mx, o));
        float se = 0.f;
        #pragma unroll
        for (int j = 0; j < 4; j++) {
            int c = tx * 4 + j;
            if (c < NCLASS) se += __expf(l[j] - mx);
        }
        #pragma unroll
        for (int o = 8; o > 0; o >>= 1)
            se += __shfl_xor_sync(0xffffffffu, se, o);
        float ls = mx + __logf(se);
        if (row < Nrows) {
            #pragma unroll
            for (int j = 0; j < 4; j++) {
                int c = tx * 4 + j;
                if (c < NCLASS) out[(size_t)row * NCLASS + c] = l[j] - ls;
            }
        }
    }
}

// ---------------- CSR SpMM (fp16 gather) fused with SAGE epilogue -----------
__global__ void spmm_relu_kernel(const __half* __restrict__ P,
                                 const float* __restrict__ S,
                                 float* __restrict__ H)
{
    int warp = (blockIdx.x * blockDim.x + threadIdx.x) >> 5;
    int lane = threadIdx.x & 31;
    if (warp >= NNODES) return;
    int r = warp;
    int start = g_rowptr[r], end = g_rowptr[r + 1];

    float4 acc = make_float4(0.f, 0.f, 0.f, 0.f);
    for (int base = start; base < end; base += 32) {
        int idx = base + lane;
        int c = (idx < end) ? g_colidx[idx] : 0;
        int cnt = min(32, end - base);
        #pragma unroll 4
        for (int j = 0; j < cnt; j++) {
            int cj = __shfl_sync(0xffffffffu, c, j);
            uint2 raw = *reinterpret_cast<const uint2*>(P + (size_t)cj * 128 + lane * 4);
            float2 f0 = __half22float2(*reinterpret_cast<__half2*>(&raw.x));
            float2 f1 = __half22float2(*reinterpret_cast<__half2*>(&raw.y));
            acc.x += f0.x; acc.y += f0.y; acc.z += f1.x; acc.w += f1.y;
        }
    }
    float inv = g_invdeg[r];
    float4 s = *reinterpret_cast<const float4*>(S + (size_t)r * 128 + lane * 4);
    float4 h;
    h.x = fmaxf(fmaf(acc.x, inv, s.x), 0.f);
    h.y = fmaxf(fmaf(acc.y, inv, s.y), 0.f);
    h.z = fmaxf(fmaf(acc.z, inv, s.z), 0.f);
    h.w = fmaxf(fmaf(acc.w, inv, s.w), 0.f);
    *reinterpret_cast<float4*>(H + (size_t)r * 128 + lane * 4) = h;
}

// ---------------- launch ----------------
extern "C" void kernel_launch(void* const* d_in, const int* in_sizes, int n_in,
                              void* d_out, int out_size) {
    const float* x     = (const float*)d_in[0];   // [N,256]
    const float* W1    = (const float*)d_in[1];   // [128,512]
    const float* W2    = (const float*)d_in[2];   // [128,256]
    const float* mlpW  = (const float*)d_in[3];   // [40,128]
    const float* mlpb  = (const float*)d_in[4];   // [40]
    const int*   erow  = (const int*)d_in[5];
    const int*   ecol  = (const int*)d_in[6];
    int E = in_sizes[5];
    float* out = (float*)d_out;

    float *pSelf, *pH;
    __half* pPh;
    cudaGetSymbolAddress((void**)&pSelf, g_Self);
    cudaGetSymbolAddress((void**)&pPh, g_Ph);
    cudaGetSymbolAddress((void**)&pH, g_H);

    // one-time setup (no device memory allocation involved)
    static cudaStream_t s_gemm = nullptr;
    static cudaEvent_t  ev_fork = nullptr, ev_join = nullptr;
    if (s_gemm == nullptr) {
        cudaStreamCreateWithFlags(&s_gemm, cudaStreamNonBlocking);
        cudaEventCreateWithFlags(&ev_fork, cudaEventDisableTiming);
        cudaEventCreateWithFlags(&ev_join, cudaEventDisableTiming);
        cudaFuncSetAttribute(mma_gemm_kernel,
                             cudaFuncAttributeMaxDynamicSharedMemorySize, GEMM_SMEM_BYTES);
    }

    const int nb_nodes = (NNODES + 255) / 256;
    const int nb_edges = (E + 255) / 256;
    const int nb_warps = (NNODES * 32 + 255) / 256;
    const int nb_tiles = (NNODES + 127) / 128;
    dim3 g1(nb_tiles, 2);

    // Fork: layer-1 GEMM on side stream, CSR build on main stream (independent)
    cudaEventRecord(ev_fork, 0);
    cudaStreamWaitEvent(s_gemm, ev_fork, 0);
    mma_gemm_kernel<<<g1, 256, GEMM_SMEM_BYTES, s_gemm>>>(x, W1, NFEAT, 2 * NFEAT,
                                                          pSelf, pPh, NNODES);
    cudaEventRecord(ev_join, s_gemm);

    k_zero_deg<<<nb_nodes, 256>>>();
    k_hist<<<nb_edges, 256>>>(erow, E);
    k_scan<<<1, 1024>>>();
    k_aux<<<nb_nodes, 256>>>();
    k_scatter<<<nb_edges, 256>>>(erow, ecol, E);

    // Join: SpMM needs both CSR and the layer-1 projections
    cudaStreamWaitEvent(0, ev_join, 0);
    spmm_relu_kernel<<<nb_warps, 256>>>(pPh, pSelf, pH);

    // Layer 2
    mma_gemm_kernel<<<g1, 256, GEMM_SMEM_BYTES>>>(pH, W2, NHID, 2 * NHID,
                                                  pSelf, pPh, NNODES);
    spmm_relu_kernel<<<nb_warps, 256>>>(pPh, pSelf, pH);

    cls_kernel<<<(NNODES + 127) / 128, 256>>>(pH, mlpW, mlpb, out, NNODES);
}

// round 9
// speedup vs baseline: 2.6526x; 1.1302x over previous
#include <cuda_runtime.h>
#include <cuda_fp16.h>
#include <cstdint>
#include <math.h>

#define NNODES 100000
#define NEDGES 3200000
#define NFEAT  256
#define NHID   128
#define NCLASS 40

#define SCAN_B  1024
#define SCAN_NB ((NNODES + SCAN_B - 1) / SCAN_B)   // 98

// ---------------- scratch ----------------
__device__ float  g_Self[(size_t)NNODES * NHID];
__device__ __half g_Ph[(size_t)NNODES * NHID];     // neighbor projection, fp16
__device__ float  g_H[(size_t)NNODES * NHID];
__device__ int    g_deg[NNODES];
__device__ int    g_rowptr[NNODES + 1];
__device__ int    g_cursor[NNODES];
__device__ int    g_colidx[NEDGES];
__device__ float  g_invdeg[NNODES];
__device__ int    g_blocksum[SCAN_NB];

// ---------------- CSR build ----------------
__global__ void k_zero_deg() {
    int i = blockIdx.x * blockDim.x + threadIdx.x;
    if (i < NNODES) g_deg[i] = 0;
}
__global__ void k_hist(const int* __restrict__ rows, int E) {
    int e = blockIdx.x * blockDim.x + threadIdx.x;
    if (e < E) atomicAdd(&g_deg[rows[e]], 1);
}

// Phase 1: per-block sums of deg
__global__ void k_scan1() {
    __shared__ int wsum[32];
    int tid = threadIdx.x, lane = tid & 31, wid = tid >> 5;
    int i = blockIdx.x * SCAN_B + tid;
    int v = (i < NNODES) ? g_deg[i] : 0;
    #pragma unroll
    for (int o = 16; o > 0; o >>= 1)
        v += __shfl_xor_sync(0xffffffffu, v, o);
    if (lane == 0) wsum[wid] = v;
    __syncthreads();
    if (wid == 0) {
        int y = (lane < 32) ? wsum[lane] : 0;
        #pragma unroll
        for (int o = 16; o > 0; o >>= 1)
            y += __shfl_xor_sync(0xffffffffu, y, o);
        if (lane == 0) g_blocksum[blockIdx.x] = y;
    }
}

// Phase 2: exclusive scan of the 98 block sums (one small block)
__global__ void k_scan2() {
    __shared__ int s[128];
    int tid = threadIdx.x;
    int v = (tid < SCAN_NB) ? g_blocksum[tid] : 0;
    s[tid] = v;
    __syncthreads();
    #pragma unroll
    for (int o = 1; o < 128; o <<= 1) {
        int t = (tid >= o) ? s[tid - o] : 0;
        __syncthreads();
        s[tid] += t;
        __syncthreads();
    }
    if (tid < SCAN_NB) g_blocksum[tid] = s[tid] - v;   // exclusive
    if (tid == 127) g_rowptr[NNODES] = s[127];
}

// Phase 3: block-wide exclusive scan + block offset; fused aux init
__global__ void k_scan3() {
    __shared__ int wsum[32];
    int tid = threadIdx.x, lane = tid & 31, wid = tid >> 5;
    int i = blockIdx.x * SCAN_B + tid;
    int v = (i < NNODES) ? g_deg[i] : 0;
    int x = v;
    #pragma unroll
    for (int o = 1; o < 32; o <<= 1) {
        int t = __shfl_up_sync(0xffffffffu, x, o);
        if (lane >= o) x += t;
    }
    if (lane == 31) wsum[wid] = x;
    __syncthreads();
    if (wid == 0) {
        int y = wsum[lane];
        #pragma unroll
        for (int o = 1; o < 32; o <<= 1) {
            int t = __shfl_up_sync(0xffffffffu, y, o);
            if (lane >= o) y += t;
        }
        wsum[lane] = y;
    }
    __syncthreads();
    if (i < NNODES) {
        int incl = x + (wid > 0 ? wsum[wid - 1] : 0) + g_blocksum[blockIdx.x];
        int excl = incl - v;
        g_rowptr[i] = excl;
        g_cursor[i] = excl;
        g_invdeg[i] = 1.0f / ((float)v + 1.0f);
    }
}

__global__ void k_scatter(const int* __restrict__ rows, const int* __restrict__ cols, int E) {
    int e = blockIdx.x * blockDim.x + threadIdx.x;
    if (e < E) {
        int r = rows[e];
        int p = atomicAdd(&g_cursor[r], 1);
        g_colidx[p] = cols[e];
    }
}

// ================= tf32 mma.sync GEMM, cp.async double-buffered =============
// y = blockIdx.y: 0 -> C0 fp32 (self slab of W), 1 -> C1h fp16 (neigh slab).
#define ABUF_F 4608            // 128*36 floats per stage
#define SMEM_FLOATS (4 * ABUF_F)
#define GEMM_SMEM_BYTES (SMEM_FLOATS * 4)

__global__ __launch_bounds__(256, 2) void mma_gemm_kernel(
    const float* __restrict__ A, const float* __restrict__ W,
    int K, int ldb,
    float* __restrict__ C0, __half* __restrict__ C1h, int Nrows)
{
    extern __shared__ float smemf[];   // [2][128][36] A, then [2][128][36] B
    const int tid = threadIdx.x;
    const int lane = tid & 31, wid = tid >> 5;
    const int warp_m = wid & 3;
    const int warp_n = wid >> 2;
    const int gid = lane >> 2, tig = lane & 3;
    const int tile0 = blockIdx.x * 128;
    const float* Bp = W + (size_t)blockIdx.y * K;
    const uint32_t smem_u32 = (uint32_t)__cvta_generic_to_shared(smemf);

    float acc[2][8][4];
    #pragma unroll
    for (int mi = 0; mi < 2; mi++)
        #pragma unroll
        for (int ni = 0; ni < 8; ni++)
            #pragma unroll
            for (int q = 0; q < 4; q++) acc[mi][ni][q] = 0.f;

    const int srow = tid >> 3;
    const int skq  = (tid & 7) << 2;
    int gr0 = tile0 + srow;

    auto stage = [&](int s, int kc) {
        #pragma unroll
        for (int it = 0; it < 4; it++) {
            int row = srow + (it << 5);
            int gr = gr0 + (it << 5);
            if (gr >= Nrows) gr = Nrows - 1;
            const float* ga = A + (size_t)gr * K + kc + skq;
            uint32_t da = smem_u32 + (uint32_t)((s * ABUF_F + row * 36 + skq) << 2);
            asm volatile("cp.async.ca.shared.global [%0], [%1], 16;" :: "r"(da), "l"(ga));
            const float* gb = Bp + (size_t)row * ldb + kc + skq;
            uint32_t db = smem_u32 + (uint32_t)(((2 * ABUF_F) + s * ABUF_F + row * 36 + skq) << 2);
            asm volatile("cp.async.ca.shared.global [%0], [%1], 16;" :: "r"(db), "l"(gb));
        }
        asm volatile("cp.async.commit_group;");
    };

    const int nch = K >> 5;
    stage(0, 0);

    for (int ch = 0; ch < nch; ch++) {
        const int s = ch & 1;
        if (ch + 1 < nch) {
            stage(s ^ 1, (ch + 1) << 5);
            asm volatile("cp.async.wait_group 1;");
        } else {
            asm volatile("cp.async.wait_group 0;");
        }
        __syncthreads();

        const float* Abuf = smemf + s * ABUF_F;
        const float* Bbuf = smemf + 2 * ABUF_F + s * ABUF_F;

        #pragma unroll
        for (int kb = 0; kb < 32; kb += 8) {
            uint32_t a[2][4];
            #pragma unroll
            for (int mi = 0; mi < 2; mi++) {
                int R = warp_m * 32 + mi * 16;
                a[mi][0] = __float_as_uint(Abuf[(R + gid) * 36 + kb + tig]);
                a[mi][1] = __float_as_uint(Abuf[(R + gid + 8) * 36 + kb + tig]);
                a[mi][2] = __float_as_uint(Abuf[(R + gid) * 36 + kb + tig + 4]);
                a[mi][3] = __float_as_uint(Abuf[(R + gid + 8) * 36 + kb + tig + 4]);
            }
            #pragma unroll
            for (int ni = 0; ni < 8; ni++) {
                int n0 = warp_n * 64 + ni * 8;
                uint32_t b0 = __float_as_uint(Bbuf[(n0 + gid) * 36 + kb + tig]);
                uint32_t b1 = __float_as_uint(Bbuf[(n0 + gid) * 36 + kb + tig + 4]);
                #pragma unroll
                for (int mi = 0; mi < 2; mi++) {
                    asm volatile(
                        "mma.sync.aligned.m16n8k8.row.col.f32.tf32.tf32.f32 "
                        "{%0,%1,%2,%3}, {%4,%5,%6,%7}, {%8,%9}, {%0,%1,%2,%3};"
                        : "+f"(acc[mi][ni][0]), "+f"(acc[mi][ni][1]),
                          "+f"(acc[mi][ni][2]), "+f"(acc[mi][ni][3])
                        : "r"(a[mi][0]), "r"(a[mi][1]), "r"(a[mi][2]), "r"(a[mi][3]),
                          "r"(b0), "r"(b1));
                }
            }
        }
        __syncthreads();
    }

    const bool half_out = (blockIdx.y != 0);
    #pragma unroll
    for (int mi = 0; mi < 2; mi++) {
        int r0 = tile0 + warp_m * 32 + mi * 16 + gid;
        #pragma unroll
        for (int ni = 0; ni < 8; ni++) {
            int c = warp_n * 64 + ni * 8 + tig * 2;
            if (half_out) {
                if (r0 < Nrows)
                    *reinterpret_cast<__half2*>(C1h + (size_t)r0 * 128 + c) =
                        __floats2half2_rn(acc[mi][ni][0], acc[mi][ni][1]);
                if (r0 + 8 < Nrows)
                    *reinterpret_cast<__half2*>(C1h + (size_t)(r0 + 8) * 128 + c) =
                        __floats2half2_rn(acc[mi][ni][2], acc[mi][ni][3]);
            } else {
                if (r0 < Nrows)
                    *reinterpret_cast<float2*>(C0 + (size_t)r0 * 128 + c) =
                        make_float2(acc[mi][ni][0], acc[mi][ni][1]);
                if (r0 + 8 < Nrows)
                    *reinterpret_cast<float2*>(C0 + (size_t)(r0 + 8) * 128 + c) =
                        make_float2(acc[mi][ni][2], acc[mi][ni][3]);
            }
        }
    }
}

// ---------------- Classifier GEMM fused with bias + log_softmax -------------
__global__ __launch_bounds__(256, 2) void cls_kernel(
    const float* __restrict__ A, const float* __restrict__ W,
    const float* __restrict__ bias, float* __restrict__ out, int Nrows)
{
    __shared__ float As[8][128];
    __shared__ float Bs[8][64];

    int tid = threadIdx.x;
    int n0 = blockIdx.x * 128;
    int tx = tid & 15, ty = tid >> 4;

    float acc[8][4];
    #pragma unroll
    for (int i = 0; i < 8; i++)
        #pragma unroll
        for (int j = 0; j < 4; j++) acc[i][j] = 0.f;

    int aRow = tid >> 1;
    int aCol = (tid & 1) * 4;
    bool aValid = (n0 + aRow) < Nrows;
    const float* Aptr = A + (size_t)(n0 + aRow) * NHID + aCol;

    int bRow = tid >> 1;
    int bCol = (tid & 1) * 4;
    const float* Bptr = (tid < 128 && bRow < NCLASS) ? W + (size_t)bRow * NHID + bCol : nullptr;

    for (int k0 = 0; k0 < NHID; k0 += 8) {
        float4 av = aValid ? *reinterpret_cast<const float4*>(Aptr + k0)
                           : make_float4(0.f, 0.f, 0.f, 0.f);
        As[aCol + 0][aRow] = av.x; As[aCol + 1][aRow] = av.y;
        As[aCol + 2][aRow] = av.z; As[aCol + 3][aRow] = av.w;
        if (tid < 128) {
            float4 bv = Bptr ? *reinterpret_cast<const float4*>(Bptr + k0)
                             : make_float4(0.f, 0.f, 0.f, 0.f);
            Bs[bCol + 0][bRow] = bv.x; Bs[bCol + 1][bRow] = bv.y;
            Bs[bCol + 2][bRow] = bv.z; Bs[bCol + 3][bRow] = bv.w;
        }
        __syncthreads();

        #pragma unroll
        for (int k = 0; k < 8; k++) {
            float a[8], b[4];
            *reinterpret_cast<float4*>(a)     = *reinterpret_cast<float4*>(&As[k][ty * 8]);
            *reinterpret_cast<float4*>(a + 4) = *reinterpret_cast<float4*>(&As[k][ty * 8 + 4]);
            *reinterpret_cast<float4*>(b)     = *reinterpret_cast<float4*>(&Bs[k][tx * 4]);
            #pragma unroll
            for (int i = 0; i < 8; i++)
                #pragma unroll
                for (int j = 0; j < 4; j++)
                    acc[i][j] = fmaf(a[i], b[j], acc[i][j]);
        }
        __syncthreads();
    }

    float bs[4];
    #pragma unroll
    for (int j = 0; j < 4; j++) {
        int c = tx * 4 + j;
        bs[j] = (c < NCLASS) ? bias[c] : 0.f;
    }

    #pragma unroll
    for (int i = 0; i < 8; i++) {
        int row = n0 + ty * 8 + i;
        float l[4];
        #pragma unroll
        for (int j = 0; j < 4; j++) {
            int c = tx * 4 + j;
            l[j] = (c < NCLASS) ? acc[i][j] + bs[j] : -INFINITY;
        }
        float mx = fmaxf(fmaxf(l[0], l[1]), fmaxf(l[2], l[3]));
        #pragma unroll
        for (int o = 8; o > 0; o >>= 1)
            mx = fmaxf(mx, __shfl_xor_sync(0xffffffffu, mx, o));
        float se = 0.f;
        #pragma unroll
        for (int j = 0; j < 4; j++) {
            int c = tx * 4 + j;
            if (c < NCLASS) se += __expf(l[j] - mx);
        }
        #pragma unroll
        for (int o = 8; o > 0; o >>= 1)
            se += __shfl_xor_sync(0xffffffffu, se, o);
        float ls = mx + __logf(se);
        if (row < Nrows) {
            #pragma unroll
            for (int j = 0; j < 4; j++) {
                int c = tx * 4 + j;
                if (c < NCLASS) out[(size_t)row * NCLASS + c] = l[j] - ls;
            }
        }
    }
}

// ---------------- CSR SpMM (fp16 gather) fused with SAGE epilogue -----------
__global__ void spmm_relu_kernel(const __half* __restrict__ P,
                                 const float* __restrict__ S,
                                 float* __restrict__ H)
{
    int warp = (blockIdx.x * blockDim.x + threadIdx.x) >> 5;
    int lane = threadIdx.x & 31;
    if (warp >= NNODES) return;
    int r = warp;
    int start = g_rowptr[r], end = g_rowptr[r + 1];

    float4 acc = make_float4(0.f, 0.f, 0.f, 0.f);
    for (int base = start; base < end; base += 32) {
        int idx = base + lane;
        int c = (idx < end) ? g_colidx[idx] : 0;
        int cnt = min(32, end - base);
        #pragma unroll 4
        for (int j = 0; j < cnt; j++) {
            int cj = __shfl_sync(0xffffffffu, c, j);
            uint2 raw = *reinterpret_cast<const uint2*>(P + (size_t)cj * 128 + lane * 4);
            float2 f0 = __half22float2(*reinterpret_cast<__half2*>(&raw.x));
            float2 f1 = __half22float2(*reinterpret_cast<__half2*>(&raw.y));
            acc.x += f0.x; acc.y += f0.y; acc.z += f1.x; acc.w += f1.y;
        }
    }
    float inv = g_invdeg[r];
    float4 s = *reinterpret_cast<const float4*>(S + (size_t)r * 128 + lane * 4);
    float4 h;
    h.x = fmaxf(fmaf(acc.x, inv, s.x), 0.f);
    h.y = fmaxf(fmaf(acc.y, inv, s.y), 0.f);
    h.z = fmaxf(fmaf(acc.z, inv, s.z), 0.f);
    h.w = fmaxf(fmaf(acc.w, inv, s.w), 0.f);
    *reinterpret_cast<float4*>(H + (size_t)r * 128 + lane * 4) = h;
}

// ---------------- launch ----------------
extern "C" void kernel_launch(void* const* d_in, const int* in_sizes, int n_in,
                              void* d_out, int out_size) {
    const float* x     = (const float*)d_in[0];   // [N,256]
    const float* W1    = (const float*)d_in[1];   // [128,512]
    const float* W2    = (const float*)d_in[2];   // [128,256]
    const float* mlpW  = (const float*)d_in[3];   // [40,128]
    const float* mlpb  = (const float*)d_in[4];   // [40]
    const int*   erow  = (const int*)d_in[5];
    const int*   ecol  = (const int*)d_in[6];
    int E = in_sizes[5];
    float* out = (float*)d_out;

    float *pSelf, *pH;
    __half* pPh;
    cudaGetSymbolAddress((void**)&pSelf, g_Self);
    cudaGetSymbolAddress((void**)&pPh, g_Ph);
    cudaGetSymbolAddress((void**)&pH, g_H);

    static cudaStream_t s_gemm = nullptr;
    static cudaEvent_t  ev_fork = nullptr, ev_join = nullptr;
    if (s_gemm == nullptr) {
        cudaStreamCreateWithFlags(&s_gemm, cudaStreamNonBlocking);
        cudaEventCreateWithFlags(&ev_fork, cudaEventDisableTiming);
        cudaEventCreateWithFlags(&ev_join, cudaEventDisableTiming);
        cudaFuncSetAttribute(mma_gemm_kernel,
                             cudaFuncAttributeMaxDynamicSharedMemorySize, GEMM_SMEM_BYTES);
    }

    const int nb_nodes = (NNODES + 255) / 256;
    const int nb_edges = (E + 255) / 256;
    const int nb_warps = (NNODES * 32 + 255) / 256;
    const int nb_tiles = (NNODES + 127) / 128;
    dim3 g1(nb_tiles, 2);

    // Fork: layer-1 GEMM on side stream, CSR build on main stream (independent)
    cudaEventRecord(ev_fork, 0);
    cudaStreamWaitEvent(s_gemm, ev_fork, 0);
    mma_gemm_kernel<<<g1, 256, GEMM_SMEM_BYTES, s_gemm>>>(x, W1, NFEAT, 2 * NFEAT,
                                                          pSelf, pPh, NNODES);
    cudaEventRecord(ev_join, s_gemm);

    k_zero_deg<<<nb_nodes, 256>>>();
    k_hist<<<nb_edges, 256>>>(erow, E);
    k_scan1<<<SCAN_NB, SCAN_B>>>();
    k_scan2<<<1, 128>>>();
    k_scan3<<<SCAN_NB, SCAN_B>>>();
    k_scatter<<<nb_edges, 256>>>(erow, ecol, E);

    // Join: SpMM needs both CSR and the layer-1 projections
    cudaStreamWaitEvent(0, ev_join, 0);
    spmm_relu_kernel<<<nb_warps, 256>>>(pPh, pSelf, pH);

    // Layer 2
    mma_gemm_kernel<<<g1, 256, GEMM_SMEM_BYTES>>>(pH, W2, NHID, 2 * NHID,
                                                  pSelf, pPh, NNODES);
    spmm_relu_kernel<<<nb_warps, 256>>>(pPh, pSelf, pH);

    cls_kernel<<<(NNODES + 127) / 128, 256>>>(pH, mlpW, mlpb, out, NNODES);
}